// round 6
// baseline (speedup 1.0000x reference)
#include <cuda_runtime.h>

typedef unsigned long long u64;

#define THREADS 128
#define NPTS 2                          // points per thread
#define PTS_PER_BLOCK (THREADS * NPTS)
#define HIDDEN 16
#define NLAYERS 8

// Single packed constant bank. Warp-uniform reads -> LDCU through the
// dedicated uniform-constant port (floor=1/SMSP), zero L1 traffic.
#define OFF_WIN  0      // [j][c], 32
#define OFF_BIN  32     // [j], 16
#define OFF_WOUT 48     // [j][k], 48
#define OFF_WH   96     // [l][j][k], 2048
#define CW_TOTAL 2144
__constant__ float cW[CW_TOTAL];

// ---------- f32x2 packed-math helpers (sm_103a) ----------
__device__ __forceinline__ u64 pack2(float lo, float hi) {
    u64 r; asm("mov.b64 %0, {%1, %2};" : "=l"(r) : "f"(lo), "f"(hi)); return r;
}
__device__ __forceinline__ void unpack2(u64 a, float& lo, float& hi) {
    asm("mov.b64 {%0, %1}, %2;" : "=f"(lo), "=f"(hi) : "l"(a));
}
__device__ __forceinline__ u64 ffma2(u64 a, u64 b, u64 c) {
    u64 d; asm("fma.rn.f32x2 %0, %1, %2, %3;" : "=l"(d) : "l"(a), "l"(b), "l"(c)); return d;
}
__device__ __forceinline__ u64 fmul2(u64 a, u64 b) {
    u64 d; asm("mul.rn.f32x2 %0, %1, %2;" : "=l"(d) : "l"(a), "l"(b)); return d;
}
__device__ __forceinline__ float tanh_hw(float x) {
    float r; asm("tanh.approx.f32 %0, %1;" : "=f"(r) : "f"(x)); return r;
}
__device__ __forceinline__ float sigmoid_hw(float x) {
    return fmaf(tanh_hw(0.5f * x), 0.5f, 0.5f);
}

// Stage weights into the constant bank through its global alias. The data is
// identical on every call, so replays are deterministic even if a per-SM
// constant cache holds a previous (identical) copy.
__global__ void stage_weights(const float* __restrict__ W_in,
                              const float* __restrict__ b_in,
                              const float* __restrict__ W_h,
                              const float* __restrict__ W_out,
                              float* __restrict__ dst)
{
    int t = threadIdx.x;
    if (t < 32)        dst[OFF_WIN + t] = W_in[t];
    else if (t < 48)   dst[OFF_BIN + t - 32] = b_in[t - 32];
    else if (t < 96)   dst[OFF_WOUT + t - 48] = W_out[t - 48];
    for (int i = t; i < NLAYERS * 256; i += blockDim.x)
        dst[OFF_WH + i] = W_h[i];
}

__global__ void __launch_bounds__(THREADS, 6)
mlp_kernel(const float* __restrict__ x,
           float* __restrict__ out)
{
    const int tid = threadIdx.x;
    const int base = blockIdx.x * PTS_PER_BLOCK + tid;

    const float2* __restrict__ xp = (const float2*)x;
    float2 xv[NPTS];
    #pragma unroll
    for (int p = 0; p < NPTS; p++) xv[p] = xp[base + p * THREADS];

    // h[p][kk] holds the activation pair (h_{2kk}, h_{2kk+1})
    u64 h[NPTS][8];

    // ---- input layer: h_j = tanh(x0*W[j][0] + x1*W[j][1] + b_j) ----
    {
        const u64* __restrict__ win = (const u64*)&cW[OFF_WIN]; // (W[j][0],W[j][1])
        #pragma unroll
        for (int p = 0; p < NPTS; p++) {
            u64 xpair = pack2(xv[p].x, xv[p].y);
            #pragma unroll
            for (int jj = 0; jj < 8; jj++) {
                u64 ma = fmul2(xpair, win[2 * jj]);
                u64 mb = fmul2(xpair, win[2 * jj + 1]);
                float a0, a1, b0, b1;
                unpack2(ma, a0, a1);
                unpack2(mb, b0, b1);
                float sa = a0 + a1 + cW[OFF_BIN + 2 * jj];
                float sb = b0 + b1 + cW[OFF_BIN + 2 * jj + 1];
                h[p][jj] = pack2(tanh_hw(sa), tanh_hw(sb));
            }
        }
    }

    // ---- 8 hidden layers: h' = tanh(h @ W^T) ----
    #pragma unroll 1
    for (int l = 0; l < NLAYERS; l++) {
        const u64* __restrict__ wl = (const u64*)&cW[OFF_WH + l * 256]; // [j*8+kk]
        u64 hn[NPTS][8];
        #pragma unroll
        for (int jj = 0; jj < 8; jj++) {
            const u64* __restrict__ wa = wl + (2 * jj) * 8;
            const u64* __restrict__ wb = wl + (2 * jj + 1) * 8;
            #pragma unroll
            for (int p = 0; p < NPTS; p++) {
                u64 acc_a = fmul2(h[p][0], wa[0]);
                u64 acc_b = fmul2(h[p][0], wb[0]);
                #pragma unroll
                for (int kk = 1; kk < 8; kk++) {
                    acc_a = ffma2(h[p][kk], wa[kk], acc_a);
                    acc_b = ffma2(h[p][kk], wb[kk], acc_b);
                }
                // Horizontal sums as scalar FADDs on the free pair halves;
                // tanh outputs packed directly into the next-layer pair.
                float a0, a1, b0, b1;
                unpack2(acc_a, a0, a1);
                unpack2(acc_b, b0, b1);
                float sa = a0 + a1;
                float sb = b0 + b1;
                hn[p][jj] = pack2(tanh_hw(sa), tanh_hw(sb));
            }
        }
        #pragma unroll
        for (int p = 0; p < NPTS; p++)
            #pragma unroll
            for (int jj = 0; jj < 8; jj++) h[p][jj] = hn[p][jj];
    }

    // ---- output layer: sigmoid(h @ W_out^T), 16 -> 3 ----
    #pragma unroll
    for (int p = 0; p < NPTS; p++) {
        int pt = base + p * THREADS;
        const u64* __restrict__ wo = (const u64*)&cW[OFF_WOUT]; // [j*8+kk]
        #pragma unroll
        for (int j = 0; j < 3; j++) {
            u64 acc = fmul2(h[p][0], wo[j * 8]);
            #pragma unroll
            for (int kk = 1; kk < 8; kk++)
                acc = ffma2(h[p][kk], wo[j * 8 + kk], acc);
            float a0, a1; unpack2(acc, a0, a1);
            out[pt * 3 + j] = sigmoid_hw(a0 + a1);
        }
    }
}

extern "C" void kernel_launch(void* const* d_in, const int* in_sizes, int n_in,
                              void* d_out, int out_size) {
    const float* x     = (const float*)d_in[0];
    const float* W_in  = (const float*)d_in[1];
    const float* b_in  = (const float*)d_in[2];
    const float* W_h   = (const float*)d_in[3];
    const float* W_out = (const float*)d_in[4];
    float* out = (float*)d_out;

    void* cw_addr = nullptr;
    cudaGetSymbolAddress(&cw_addr, cW);

    stage_weights<<<1, 256>>>(W_in, b_in, W_h, W_out, (float*)cw_addr);

    int n_points = in_sizes[0] / 2;               // x is [N,2]
    int blocks = n_points / PTS_PER_BLOCK;        // 4194304 / 256 = 16384, exact
    mlp_kernel<<<blocks, THREADS>>>(x, out);
}

// round 7
// speedup vs baseline: 1.3662x; 1.3662x over previous
#include <cuda_runtime.h>

typedef unsigned long long u64;

#define THREADS 128
#define NPTS 2                          // points per thread
#define PTS_PER_BLOCK (THREADS * NPTS)
#define HIDDEN 16
#define NLAYERS 8

// Single packed constant bank. Warp-uniform reads -> uniform-constant port
// (LDCU/ULDC, floor=1/SMSP), zero L1 traffic.
#define OFF_WIN  0      // [j][c], 32
#define OFF_BIN  32     // [j], 16
#define OFF_WOUT 48     // [j][k], 48
#define OFF_WH   96     // [l][j][k], 2048
#define CW_TOTAL 2144
__constant__ __align__(16) float cW[CW_TOTAL];

// ---------- f32x2 packed-math helpers (sm_103a) ----------
__device__ __forceinline__ u64 pack2(float lo, float hi) {
    u64 r; asm("mov.b64 %0, {%1, %2};" : "=l"(r) : "f"(lo), "f"(hi)); return r;
}
__device__ __forceinline__ void unpack2(u64 a, float& lo, float& hi) {
    asm("mov.b64 {%0, %1}, %2;" : "=f"(lo), "=f"(hi) : "l"(a));
}
__device__ __forceinline__ u64 ffma2(u64 a, u64 b, u64 c) {
    u64 d; asm("fma.rn.f32x2 %0, %1, %2, %3;" : "=l"(d) : "l"(a), "l"(b), "l"(c)); return d;
}
__device__ __forceinline__ u64 fmul2(u64 a, u64 b) {
    u64 d; asm("mul.rn.f32x2 %0, %1, %2;" : "=l"(d) : "l"(a), "l"(b)); return d;
}
__device__ __forceinline__ float tanh_hw(float x) {
    float r; asm("tanh.approx.f32 %0, %1;" : "=f"(r) : "f"(x)); return r;
}
__device__ __forceinline__ float sigmoid_hw(float x) {
    return fmaf(tanh_hw(0.5f * x), 0.5f, 0.5f);
}

// Stage weights into the constant bank through its global alias. Identical
// data every call -> deterministic replays even with warm constant caches.
__global__ void stage_weights(const float* __restrict__ W_in,
                              const float* __restrict__ b_in,
                              const float* __restrict__ W_h,
                              const float* __restrict__ W_out,
                              float* __restrict__ dst)
{
    int t = threadIdx.x;
    if (t < 32)        dst[OFF_WIN + t] = W_in[t];
    else if (t < 48)   dst[OFF_BIN + t - 32] = b_in[t - 32];
    else if (t < 96)   dst[OFF_WOUT + t - 48] = W_out[t - 48];
    for (int i = t; i < NLAYERS * 256; i += blockDim.x)
        dst[OFF_WH + i] = W_h[i];
}

__global__ void __launch_bounds__(THREADS, 5)
mlp_kernel(const float* __restrict__ x,
           float* __restrict__ out)
{
    const int tid = threadIdx.x;
    const int base = blockIdx.x * PTS_PER_BLOCK + tid;

    const float2* __restrict__ xp = (const float2*)x;
    float2 xv[NPTS];
    #pragma unroll
    for (int p = 0; p < NPTS; p++) xv[p] = xp[base + p * THREADS];

    // h[p][kk] holds the activation pair (h_{2kk}, h_{2kk+1})
    u64 h[NPTS][8];

    // ---- input layer: h_j = tanh(x0*W[j][0] + x1*W[j][1] + b_j) ----
    {
        const u64* __restrict__ win = (const u64*)&cW[OFF_WIN]; // (W[j][0],W[j][1])
        #pragma unroll
        for (int p = 0; p < NPTS; p++) {
            u64 xpair = pack2(xv[p].x, xv[p].y);
            #pragma unroll
            for (int jj = 0; jj < 8; jj++) {
                u64 ma = fmul2(xpair, win[2 * jj]);
                u64 mb = fmul2(xpair, win[2 * jj + 1]);
                float a0, a1, b0, b1;
                unpack2(ma, a0, a1);
                unpack2(mb, b0, b1);
                float sa = a0 + a1 + cW[OFF_BIN + 2 * jj];
                float sb = b0 + b1 + cW[OFF_BIN + 2 * jj + 1];
                h[p][jj] = pack2(tanh_hw(sa), tanh_hw(sb));
            }
        }
    }

    // ---- 8 hidden layers: h' = tanh(h @ W^T) ----
    #pragma unroll 1
    for (int l = 0; l < NLAYERS; l++) {
        // 128-bit uniform-port reads: each ulonglong2 = 2 weight pairs.
        const ulonglong2* __restrict__ wl =
            (const ulonglong2*)&cW[OFF_WH + l * 256];   // [j*4 + kk2]
        u64 hn[NPTS][8];
        #pragma unroll
        for (int jj = 0; jj < 8; jj++) {
            const ulonglong2* __restrict__ wa = wl + (2 * jj) * 4;
            const ulonglong2* __restrict__ wb = wl + (2 * jj + 1) * 4;
            #pragma unroll
            for (int p = 0; p < NPTS; p++) {
                ulonglong2 wa0 = wa[0], wb0 = wb[0];
                u64 acc_a = fmul2(h[p][0], wa0.x);
                u64 acc_b = fmul2(h[p][0], wb0.x);
                acc_a = ffma2(h[p][1], wa0.y, acc_a);
                acc_b = ffma2(h[p][1], wb0.y, acc_b);
                #pragma unroll
                for (int kk2 = 1; kk2 < 4; kk2++) {
                    ulonglong2 wav = wa[kk2], wbv = wb[kk2];
                    acc_a = ffma2(h[p][2 * kk2],     wav.x, acc_a);
                    acc_b = ffma2(h[p][2 * kk2],     wbv.x, acc_b);
                    acc_a = ffma2(h[p][2 * kk2 + 1], wav.y, acc_a);
                    acc_b = ffma2(h[p][2 * kk2 + 1], wbv.y, acc_b);
                }
                // Horizontal sums as scalar FADDs on the free pair halves;
                // tanh outputs packed directly into the next-layer pair.
                float a0, a1, b0, b1;
                unpack2(acc_a, a0, a1);
                unpack2(acc_b, b0, b1);
                hn[p][jj] = pack2(tanh_hw(a0 + a1), tanh_hw(b0 + b1));
            }
        }
        #pragma unroll
        for (int p = 0; p < NPTS; p++)
            #pragma unroll
            for (int jj = 0; jj < 8; jj++) h[p][jj] = hn[p][jj];
    }

    // ---- output layer: sigmoid(h @ W_out^T), 16 -> 3 ----
    #pragma unroll
    for (int p = 0; p < NPTS; p++) {
        int pt = base + p * THREADS;
        const ulonglong2* __restrict__ wo = (const ulonglong2*)&cW[OFF_WOUT];
        #pragma unroll
        for (int j = 0; j < 3; j++) {
            ulonglong2 w0 = wo[j * 4];
            u64 acc = fmul2(h[p][0], w0.x);
            acc = ffma2(h[p][1], w0.y, acc);
            #pragma unroll
            for (int kk2 = 1; kk2 < 4; kk2++) {
                ulonglong2 wv = wo[j * 4 + kk2];
                acc = ffma2(h[p][2 * kk2],     wv.x, acc);
                acc = ffma2(h[p][2 * kk2 + 1], wv.y, acc);
            }
            float a0, a1; unpack2(acc, a0, a1);
            out[pt * 3 + j] = sigmoid_hw(a0 + a1);
        }
    }
}

extern "C" void kernel_launch(void* const* d_in, const int* in_sizes, int n_in,
                              void* d_out, int out_size) {
    const float* x     = (const float*)d_in[0];
    const float* W_in  = (const float*)d_in[1];
    const float* b_in  = (const float*)d_in[2];
    const float* W_h   = (const float*)d_in[3];
    const float* W_out = (const float*)d_in[4];
    float* out = (float*)d_out;

    void* cw_addr = nullptr;
    cudaGetSymbolAddress(&cw_addr, cW);

    stage_weights<<<1, 256>>>(W_in, b_in, W_h, W_out, (float*)cw_addr);

    int n_points = in_sizes[0] / 2;               // x is [N,2]
    int blocks = n_points / PTS_PER_BLOCK;        // 4194304 / 256 = 16384, exact
    mlp_kernel<<<blocks, THREADS>>>(x, out);
}